// round 16
// baseline (speedup 1.0000x reference)
#include <cuda_runtime.h>
#include <math.h>
#include <stdint.h>

#define FIN 256
#define ND  16
#define XS_STRIDE 20     // patch row stride in floats (conflict-free A-frag LDS)
#define B_STRIDE  260    // B row stride in floats (conflict-free B-frag LDS)

// scratch (static device arrays — no allocations)
__device__ float g_Bh[ND*FIN];          // tf32-high of A^T: [n][k]
__device__ float g_Bl[ND*FIN];          // residual (A - Ah): [n][k]
__device__ float g_c [ND];
__device__ float g_kw[9*ND];            // BN-folded depthwise weights [tap][d]
__device__ float g_kb[ND];              // BN-folded bias
__device__ float g_y [2*256*256*ND];    // intermediate y grid (8 MB)

__device__ __forceinline__ uint32_t smem_u32(const void* p) {
    uint32_t a;
    asm("{ .reg .u64 t; cvta.to.shared.u64 t, %1; cvt.u32.u64 %0, t; }"
        : "=r"(a) : "l"(p));
    return a;
}
__device__ __forceinline__ void cp_async16(uint32_t dst, const void* src) {
    asm volatile("cp.async.cg.shared.global [%0], [%1], 16;" :: "r"(dst), "l"(src));
}
// tf32 tensor-core MMA (HMMA.1688.F32.TF32): D(16x8) += A(16x8) * B(8x8)
__device__ __forceinline__ void mma_tf32(float* c, const uint32_t* a, const uint32_t* b) {
    asm volatile(
        "mma.sync.aligned.m16n8k8.row.col.f32.tf32.tf32.f32 "
        "{%0,%1,%2,%3}, {%4,%5,%6,%7}, {%8,%9}, {%0,%1,%2,%3};"
        : "+f"(c[0]), "+f"(c[1]), "+f"(c[2]), "+f"(c[3])
        : "r"(a[0]), "r"(a[1]), "r"(a[2]), "r"(a[3]), "r"(b[0]), "r"(b[1]));
}

// ---------------------------------------------------------------------------
// pre (fused, parallel): grid 128 x 256. Computes A then stores as tf32-split
// B = A^T (Bh = tf32(A), Bl = A - Bh). Also c[n], BN-folded conv constants.
// ---------------------------------------------------------------------------
__global__ void __launch_bounds__(256) pre_kernel(const float* __restrict__ Wr,
                                                  const float* __restrict__ Wi,
                                                  const float* __restrict__ br,
                                                  const float* __restrict__ bi,
                                                  const float* __restrict__ dwk,
                                                  const float* __restrict__ dwb,
                                                  const float* __restrict__ gamma,
                                                  const float* __restrict__ beta,
                                                  const float* __restrict__ mmean,
                                                  const float* __restrict__ mvar)
{
    __shared__ float ct[256], st[256];
    __shared__ float gsr[32], gsi[32];   // block-local G: [kl*16 + d]
    int tid = threadIdx.x;
    {
        float ang = 6.283185307179586f * (float)tid / 256.0f;
        float s, c; sincosf(ang, &s, &c);
        ct[tid] = c; st[tid] = s;
    }
    __syncthreads();

    int pair = tid >> 3;                 // 0..31 : (kl, d)
    int r    = tid & 7;                  // m-slice
    int kl   = pair >> 4;                // 0..1
    int d    = pair & 15;
    int k    = blockIdx.x * 2 + kl;      // 0..255

    float grA = 0.f, giA = 0.f, grB = 0.f, giB = 0.f;
#pragma unroll
    for (int jj = 0; jj < 16; jj++) {
        int m0 = r + jj * 16;
        int m1 = m0 + 8;
        int t0 = (m0 * k) & 255;
        int t1 = (m1 * k) & 255;
        float c0 = ct[t0], s0 = st[t0];
        float c1 = ct[t1], s1 = st[t1];
        float wr0 = Wr[m0 * 16 + d], wi0 = Wi[m0 * 16 + d];
        float wr1 = Wr[m1 * 16 + d], wi1 = Wi[m1 * 16 + d];
        grA = fmaf(c0, wr0, fmaf(s0, wi0, grA));
        giA = fmaf(c0, wi0, fmaf(-s0, wr0, giA));
        grB = fmaf(c1, wr1, fmaf(s1, wi1, grB));
        giB = fmaf(c1, wi1, fmaf(-s1, wr1, giB));
    }
    float gr = grA + grB;
    float gi = giA + giB;
#pragma unroll
    for (int off = 4; off > 0; off >>= 1) {
        gr += __shfl_down_sync(0xffffffffu, gr, off);
        gi += __shfl_down_sync(0xffffffffu, gi, off);
    }
    if (r == 0) { gsr[pair] = gr; gsi[pair] = gi; }
    __syncthreads();

    if (tid < 32) {
        int kl2 = tid >> 4;
        int n   = tid & 15;
        float acc = 0.f;
#pragma unroll
        for (int dd = 0; dd < 16; dd++) {
            int u = ((n * dd) & 15) << 4;
            acc = fmaf(gsr[kl2 * 16 + dd], ct[u], fmaf(-gsi[kl2 * 16 + dd], st[u], acc));
        }
        float a = acc * 0.0625f;
        uint32_t ahb;
        asm("cvt.rna.tf32.f32 %0, %1;" : "=r"(ahb) : "f"(a));
        float ah = __uint_as_float(ahb);
        int kk = blockIdx.x * 2 + kl2;
        g_Bh[n * 256 + kk] = ah;
        g_Bl[n * 256 + kk] = a - ah;
    }

    if (blockIdx.x == 0 && tid >= 32 && tid < 192) {
        int tt = tid - 32;
        if (tt < 16) {
            float cc = 0.f;
#pragma unroll
            for (int dd = 0; dd < 16; dd++) {
                int u = ((tt * dd) & 15) << 4;
                cc += (br[dd] - bi[dd]) * ct[u] - (br[dd] + bi[dd]) * st[u];
            }
            g_c[tt] = cc * 0.0625f;
            float scale = gamma[tt] * rsqrtf(mvar[tt] + 1e-5f);
            g_kb[tt] = (dwb[tt] - mmean[tt]) * scale + beta[tt];
        }
        if (tt < 144) {
            int dd = tt & 15;
            float scale = gamma[dd] * rsqrtf(mvar[dd] + 1e-5f);
            g_kw[tt] = dwk[tt] * scale;
        }
    }
}

// ---------------------------------------------------------------------------
// main GEMM via mma.sync tf32: y[p,n] = x[p,:].A[:,n] + c[n]
// Block = 128 thr = 4 warps = one (b, ph) row (256 patches); warp owns 64.
// R4 pipeline: warp-private 2x5KB cp.async double buffers (patch stride 20),
// no block barriers in the mainloop. B = A^T tf32-split (Bh+Bl) staged once
// in smem (row stride 260); both splits accumulate into the same fp32 C.
// Per warp: 4 Mtiles x 2 Ntiles x 32 ksteps x 2 splits = 512 HMMA.
// dyn smem: 4*2*5120 (xs) + 2*16640 (B) = 74240 B -> 3 blocks/SM.
// ---------------------------------------------------------------------------
__global__ void __launch_bounds__(128, 3) fno_gemm_kernel(const float* __restrict__ x)
{
    extern __shared__ __align__(16) float dsm[];
    float* sBh = dsm + 10240;            // 16 x 260 floats
    float* sBl = dsm + 14400;

    int t    = threadIdx.x;
    int w    = t >> 5;
    int lane = t & 31;
    int bid  = blockIdx.x;               // b*256 + ph
    int b    = bid >> 8;
    int ph   = bid & 255;

    // warp's slice of each image row: 64 patches * 16 floats
    const float* xbase = x + (size_t)(b * 4096 + ph * 16) * 4096 + w * 1024;

    uint32_t xsb = smem_u32(dsm) + (uint32_t)w * 2u * 5120u;
    uint32_t buf[2] = { xsb, xsb + 5120u };
    uint32_t dstoff[8];
#pragma unroll
    for (int it = 0; it < 8; it++) {
        int g4 = lane + it * 32;         // chunk 0..255
        int p  = g4 >> 2, c = g4 & 3;
        dstoff[it] = (uint32_t)(p * 80 + c * 16);   // stride-20 rows
    }

    // stage B (Bh+Bl) cooperatively: 2048 x 16B chunks into stride-260 rows
    {
        uint32_t bha = smem_u32(sBh), bla = smem_u32(sBl);
#pragma unroll
        for (int it = 0; it < 16; it++) {
            int ci  = t + it * 128;      // 0..2047
            int mtx = ci >> 10;
            int cj  = ci & 1023;
            int n   = cj >> 6, k4 = cj & 63;
            uint32_t dst = (mtx ? bla : bha) + (uint32_t)(n * B_STRIDE + k4 * 4) * 4u;
            const float* src = (mtx ? g_Bl : g_Bh) + n * 256 + k4 * 4;
            cp_async16(dst, src);
        }
        asm volatile("cp.async.commit_group;");
    }
    // row 0 (warp-private)
    {
        const char* src = (const char*)xbase;
#pragma unroll
        for (int it = 0; it < 8; it++)
            cp_async16(buf[0] + dstoff[it], src + ((lane + it * 32) << 4));
        asm volatile("cp.async.commit_group;");
    }
    asm volatile("cp.async.wait_group 0;");
    __syncthreads();                     // B visible block-wide

    int n0 = lane >> 2;                  // 0..7
    int kq = lane & 3;                   // 0..3
    float acc[4][2][4];
#pragma unroll
    for (int mt = 0; mt < 4; mt++)
#pragma unroll
        for (int nt = 0; nt < 2; nt++)
#pragma unroll
            for (int q = 0; q < 4; q++) acc[mt][nt][q] = 0.f;

    for (int kr = 0; kr < 16; kr++) {
        if (kr < 15) {
            uint32_t dbuf = buf[(kr + 1) & 1];
            const char* src = (const char*)(xbase + (size_t)(kr + 1) * 4096);
#pragma unroll
            for (int it = 0; it < 8; it++)
                cp_async16(dbuf + dstoff[it], src + ((lane + it * 32) << 4));
            asm volatile("cp.async.commit_group;");
            asm volatile("cp.async.wait_group 1;");   // row kr landed
        } else {
            asm volatile("cp.async.wait_group 0;");
        }
        __syncwarp();

        const float* xb = dsm + (w * 2 + (kr & 1)) * 1280;

        // B fragments for this kr: [kstep][ntile][2]
        uint32_t bh[2][2][2], bl[2][2][2];
#pragma unroll
        for (int ks = 0; ks < 2; ks++)
#pragma unroll
            for (int nt = 0; nt < 2; nt++) {
                int base = (nt * 8 + n0) * B_STRIDE + kr * 16 + ks * 8 + kq;
                bh[ks][nt][0] = __float_as_uint(sBh[base]);
                bh[ks][nt][1] = __float_as_uint(sBh[base + 4]);
                bl[ks][nt][0] = __float_as_uint(sBl[base]);
                bl[ks][nt][1] = __float_as_uint(sBl[base + 4]);
            }

#pragma unroll
        for (int mt = 0; mt < 4; mt++) {
            int r0 = (mt * 16 + n0) * XS_STRIDE;
#pragma unroll
            for (int ks = 0; ks < 2; ks++) {
                int col = ks * 8 + kq;
                uint32_t a[4];
                a[0] = __float_as_uint(xb[r0 + col]);
                a[1] = __float_as_uint(xb[r0 + 8 * XS_STRIDE + col]);
                a[2] = __float_as_uint(xb[r0 + col + 4]);
                a[3] = __float_as_uint(xb[r0 + 8 * XS_STRIDE + col + 4]);
                mma_tf32(acc[mt][0], a, bh[ks][0]);
                mma_tf32(acc[mt][0], a, bl[ks][0]);
                mma_tf32(acc[mt][1], a, bh[ks][1]);
                mma_tf32(acc[mt][1], a, bl[ks][1]);
            }
        }
        __syncwarp();                    // buffer free before re-issue
    }

    // epilogue: C frag (rows n0, n0+8; cols (kq*2, kq*2+1) per ntile) + bias
    int colb  = kq * 2;
    int prow0 = bid * 256 + w * 64 + n0;
#pragma unroll
    for (int mt = 0; mt < 4; mt++) {
#pragma unroll
        for (int nt = 0; nt < 2; nt++) {
            int col = nt * 8 + colb;
            float2 cc = *(const float2*)&g_c[col];
            float2 o0, o1;
            o0.x = acc[mt][nt][0] + cc.x; o0.y = acc[mt][nt][1] + cc.y;
            o1.x = acc[mt][nt][2] + cc.x; o1.y = acc[mt][nt][3] + cc.y;
            *(float2*)&g_y[(size_t)(prow0 + mt * 16) * 16 + col]     = o0;
            *(float2*)&g_y[(size_t)(prow0 + mt * 16 + 8) * 16 + col] = o1;
        }
    }
}

// ---------------------------------------------------------------------------
// depthwise 3x3 SAME conv (BN folded) at resized positions. One output/thread.
// ---------------------------------------------------------------------------
__global__ void __launch_bounds__(128) conv_resize_kernel(float* __restrict__ out)
{
    int lin = blockIdx.x * 128 + threadIdx.x;   // 0..131071
    int cg = lin & 3;
    int j  = (lin >> 2) & 127;
    int i  = (lin >> 9) & 127;
    int b  = lin >> 16;

    int r1 = 2 * i + 1;
    int c1 = 2 * j + 1;

    const float4* y4  = (const float4*)g_y;
    const float4* kw4 = (const float4*)g_kw;
    float4 kb = ((const float4*)g_kb)[cg];
    float sx = kb.x, sy = kb.y, sz = kb.z, sw = kb.w;

#pragma unroll
    for (int dy = -1; dy <= 1; dy++) {
        int r = r1 + dy;                         // r >= 0 always
        if (r > 255) continue;
#pragma unroll
        for (int dx = -1; dx <= 1; dx++) {
            int c = c1 + dx;                     // c >= 0 always
            if (c > 255) continue;
            float4 v = y4[((b * 256 + r) * 256 + c) * 4 + cg];
            float4 w = kw4[((dy + 1) * 3 + (dx + 1)) * 4 + cg];
            sx = fmaf(v.x, w.x, sx);
            sy = fmaf(v.y, w.y, sy);
            sz = fmaf(v.z, w.z, sz);
            sw = fmaf(v.w, w.w, sw);
        }
    }
    ((float4*)out)[((b * 128 + i) * 128 + j) * 4 + cg] = make_float4(sx, sy, sz, sw);
}

// ---------------------------------------------------------------------------
extern "C" void kernel_launch(void* const* d_in, const int* in_sizes, int n_in,
                              void* d_out, int out_size)
{
    const float* x     = (const float*)d_in[0];
    const float* Wr    = (const float*)d_in[1];
    const float* br    = (const float*)d_in[2];
    const float* Wi    = (const float*)d_in[3];
    const float* bi    = (const float*)d_in[4];
    const float* dwk   = (const float*)d_in[5];
    const float* dwb   = (const float*)d_in[6];
    const float* gamma = (const float*)d_in[7];
    const float* beta  = (const float*)d_in[8];
    const float* mmean = (const float*)d_in[9];
    const float* mvar  = (const float*)d_in[10];

    const int GEMM_SMEM = 74240;   // 40KB xs + 33.3KB B(padded)
    cudaFuncSetAttribute(fno_gemm_kernel,
                         cudaFuncAttributeMaxDynamicSharedMemorySize, GEMM_SMEM);
    cudaFuncSetAttribute(fno_gemm_kernel,
                         cudaFuncAttributePreferredSharedMemoryCarveout, 100);

    pre_kernel<<<128, 256>>>(Wr, Wi, br, bi, dwk, dwb, gamma, beta, mmean, mvar);
    fno_gemm_kernel<<<512, 128, GEMM_SMEM>>>(x);
    conv_resize_kernel<<<1024, 128>>>((float*)d_out);
}